// round 10
// baseline (speedup 1.0000x reference)
#include <cuda_runtime.h>
#include <cuda_bf16.h>
#include <cstdint>

// Problem dims
#define BB   32
#define TT   512
#define II   512
#define HH   1024
#define OO   512
#define MM   (BB*TT)

#define RNN_BLOCKS 128

// ---------------- scratch (static device globals) ---------------------------
__device__ float g_pre[MM * HH];
__device__ float g_logits[MM * OO];
__device__ float g_zfallback[MM * HH];

__device__ __nv_bfloat16 g_xhi[MM * II],    g_xlo[MM * II];
__device__ __nv_bfloat16 g_wih_hi[HH * II], g_wih_lo[HH * II];
__device__ __nv_bfloat16 g_wout_hi[OO * HH], g_wout_lo[OO * HH];
__device__ __nv_bfloat16 g_zhi[MM * HH],    g_zlo[MM * HH];
__device__ __nv_bfloat16 g_h0hi[BB * HH],   g_h0lo[BB * HH];

// per-(block, mw-half) spread flags (128B apart)
__device__ unsigned g_flags[RNN_BLOCKS * 2 * 32];

// ---------------- helpers ----------------------------------------------------
__device__ __forceinline__ void mma16816(float& d0, float& d1, float& d2, float& d3,
                                         uint32_t a0, uint32_t a1, uint32_t a2, uint32_t a3,
                                         uint32_t b0, uint32_t b1)
{
    asm volatile(
        "mma.sync.aligned.m16n8k16.row.col.f32.bf16.bf16.f32 "
        "{%0,%1,%2,%3},{%4,%5,%6,%7},{%8,%9},{%0,%1,%2,%3};"
        : "+f"(d0), "+f"(d1), "+f"(d2), "+f"(d3)
        : "r"(a0), "r"(a1), "r"(a2), "r"(a3), "r"(b0), "r"(b1));
}

__device__ __forceinline__ void ldsm4(uint32_t& r0, uint32_t& r1, uint32_t& r2, uint32_t& r3,
                                      uint32_t addr)
{
    asm volatile("ldmatrix.sync.aligned.m8n8.x4.shared.b16 {%0,%1,%2,%3}, [%4];"
                 : "=r"(r0), "=r"(r1), "=r"(r2), "=r"(r3) : "r"(addr));
}

__device__ __forceinline__ uint32_t lds32(uint32_t a) {
    uint32_t v;
    asm volatile("ld.shared.b32 %0, [%1];" : "=r"(v) : "r"(a));
    return v;
}

__device__ __forceinline__ void cpa16(uint32_t s, const void* g) {
    asm volatile("cp.async.cg.shared.global [%0], [%1], 16;" :: "r"(s), "l"(g));
}

__device__ __forceinline__ uint32_t pack_hi2(float x, float y) {
    __nv_bfloat162 t;
    t.x = __float2bfloat16(x);
    t.y = __float2bfloat16(y);
    return *reinterpret_cast<uint32_t*>(&t);
}
__device__ __forceinline__ uint32_t pack_lo2(float x, float y) {
    __nv_bfloat16 hx = __float2bfloat16(x), hy = __float2bfloat16(y);
    __nv_bfloat162 t;
    t.x = __float2bfloat16(x - __bfloat162float(hx));
    t.y = __float2bfloat16(y - __bfloat162float(hy));
    return *reinterpret_cast<uint32_t*>(&t);
}

__device__ __forceinline__ void flag_store(unsigned* p, unsigned v) {
    asm volatile("st.release.gpu.u32 [%0], %1;" :: "l"(p), "r"(v));
}
__device__ __forceinline__ void flag_wait(const unsigned* p, unsigned target) {
    unsigned v;
    do {
        asm volatile("ld.acquire.gpu.u32 %0, [%1];" : "=r"(v) : "l"(p));
    } while ((int)(v - target) < 0);
}

__device__ __forceinline__ void nbar_sync(int id, int cnt) {
    asm volatile("bar.sync %0, %1;" :: "r"(id), "r"(cnt) : "memory");
}
__device__ __forceinline__ void nbar_arrive(int id, int cnt) {
    asm volatile("bar.arrive %0, %1;" :: "r"(id), "r"(cnt) : "memory");
}

// ---------------- persistent Elman recurrence (128-block dataflow) -----------
// 128 blocks x 256 threads, 1/SM. Block jc owns j in [jc*8, jc*8+8).
// 8 warps: kw=wid&3 (k chunk of 256), mw=wid>>2 (b half of 16).
// Warp (kw,mw) polls its 32 producers' half-flags (1 per lane), stages its
// private 16x256 hi/lo slice, runs 48 HMMA, reduces in half-scope psum,
// phase B = 1 element/thread. kw=0 syncs + publishes; kw=1..3 arrive & fly.
#define WBUF   16896                   // per-warp (hi 8448 | lo 8448)
#define WB_LO  8448
#define SM_PS  (8 * WBUF)              // 135168
#define PSROW  10                      // 8 j + pad
#define PS_KW  (16 * PSROW)            // floats per kw slice
#define PS_HALF (4 * PS_KW)            // per (parity,mw)
#define RNN_SMEM (SM_PS + 4 * PS_HALF * 4)

__global__ __launch_bounds__(256, 1)
void rnn_persistent(const float* __restrict__ pre,
                    const float* __restrict__ W_hh,
                    float* __restrict__ z_out)
{
    extern __shared__ __align__(16) char dsm[];
    const uint32_t sb = (uint32_t)__cvta_generic_to_shared(dsm);

    const int tid  = threadIdx.x;
    const int wid  = tid >> 5;
    const int lane = tid & 31;
    const int grp  = lane >> 2;       // 0..7
    const int tig  = lane & 3;        // 0..3
    const int jc   = blockIdx.x;      // 0..127
    const int kw   = wid & 3;         // k chunk of 256
    const int mw   = wid >> 2;        // b half

    // replay-safe base (all flags equal at launch start)
    const unsigned base = g_flags[blockIdx.x * 64];

    // ---- preload W fragments (hi/lo) into registers, whole run ----
    uint32_t whi0[16], whi1[16], wlo0[16], wlo1[16];
    {
        const int jrow = jc * 8 + grp;
        const float* Wr = W_hh + (size_t)jrow * HH + kw * 256;
        #pragma unroll
        for (int ki = 0; ki < 16; ki++) {
            int k0 = ki * 16 + tig * 2;
            float w0 = Wr[k0],     w1 = Wr[k0 + 1];
            float w2 = Wr[k0 + 8], w3 = Wr[k0 + 9];
            whi0[ki] = pack_hi2(w0, w1);
            wlo0[ki] = pack_lo2(w0, w1);
            whi1[ki] = pack_hi2(w2, w3);
            wlo1[ki] = pack_lo2(w2, w3);
        }
    }

    // warp-private staging buffer
    const uint32_t wb = sb + (uint32_t)wid * WBUF;
    const uint32_t lrow = (lane & 7) + ((lane >> 3) & 1) * 8;
    const uint32_t aoff = lrow * 528 + ((uint32_t)lane >> 4) * 16;

    // producer half-flag this lane polls: 32 producers cover k in [kw*256,+256)
    const int pflag = ((kw * 32 + lane) * 2 + mw) * 32;

    // phase-B mapping within the 128-thread half
    const int ltid = tid & 127;
    const int lb   = ltid >> 3;               // local b 0..15
    const int pbB  = mw * 16 + lb;            // global b
    const int pbJ  = ltid & 7;                // j within chunk

    float* const psum = (float*)(dsm + SM_PS);   // [parity][mw][kw][16][PSROW]

    const int barA = 1 + mw;   // psum-ready
    const int barB = 3 + mw;   // z-done

    for (int t = 0; t < TT; t++) {
        // prefetch pre (phase-B input, independent of h)
        float pre1 = pre[((size_t)pbB * TT + t) * HH + jc * 8 + pbJ];

        // ---- dataflow wait: this warp's 32 producer half-flags ----
        if (t > 0)
            flag_wait(&g_flags[pflag], base + (unsigned)t);
        __syncwarp();

        // ---- stage own 16-row x 256-k slice: hi group, then lo group ----
        {
            const __nv_bfloat16* sh;
            const __nv_bfloat16* sl;
            size_t rstride, off0;
            if (t == 0) {
                sh = g_h0hi; sl = g_h0lo;
                rstride = HH;
                off0 = (size_t)(mw * 16) * HH + kw * 256;
            } else {
                sh = g_zhi; sl = g_zlo;
                rstride = (size_t)TT * HH;
                off0 = ((size_t)(mw * 16) * TT + (t - 1)) * HH + kw * 256;
            }
            #pragma unroll
            for (int i = 0; i < 16; i++) {
                int chunk = i * 32 + lane;
                int row   = chunk >> 5;
                int c     = chunk & 31;
                cpa16(wb + row * 528 + c * 16, sh + off0 + (size_t)row * rstride + c * 8);
            }
            asm volatile("cp.async.commit_group;" ::: "memory");
            #pragma unroll
            for (int i = 0; i < 16; i++) {
                int chunk = i * 32 + lane;
                int row   = chunk >> 5;
                int c     = chunk & 31;
                cpa16(wb + WB_LO + row * 528 + c * 16, sl + off0 + (size_t)row * rstride + c * 8);
            }
            asm volatile("cp.async.commit_group;" ::: "memory");
        }

        // hi resident; lo still in flight
        asm volatile("cp.async.wait_group 1;" ::: "memory");
        __syncwarp();

        // ---- terms 1+2: h_hi x (W_hi, W_lo) ----
        float a1[4] = {0,0,0,0};
        float a2[4] = {0,0,0,0};
        #pragma unroll
        for (int ki = 0; ki < 16; ki++) {
            uint32_t h0r, h1r, h2r, h3r;
            ldsm4(h0r, h1r, h2r, h3r, wb + aoff + ki * 32);
            mma16816(a1[0], a1[1], a1[2], a1[3],
                     h0r, h1r, h2r, h3r, whi0[ki], whi1[ki]);
            mma16816(a2[0], a2[1], a2[2], a2[3],
                     h0r, h1r, h2r, h3r, wlo0[ki], wlo1[ki]);
        }

        asm volatile("cp.async.wait_group 0;" ::: "memory");
        __syncwarp();

        // ---- term 3: h_lo x W_hi ----
        float a3[4] = {0,0,0,0};
        #pragma unroll
        for (int ki = 0; ki < 16; ki++) {
            uint32_t l0r, l1r, l2r, l3r;
            ldsm4(l0r, l1r, l2r, l3r, wb + WB_LO + aoff + ki * 32);
            mma16816(a3[0], a3[1], a3[2], a3[3],
                     l0r, l1r, l2r, l3r, whi0[ki], whi1[ki]);
        }

        // ---- per-warp k-partials to SMEM (parity double-buffered) ----
        {
            float* pb = psum + ((t & 1) * 2 + mw) * PS_HALF + kw * PS_KW;
            float c0 = a1[0] + a2[0] + a3[0];
            float c1 = a1[1] + a2[1] + a3[1];
            float c2 = a1[2] + a2[2] + a3[2];
            float c3 = a1[3] + a2[3] + a3[3];
            float* p = pb + grp * PSROW + tig * 2;
            *(float2*)p               = make_float2(c0, c1);
            *(float2*)(p + 8 * PSROW) = make_float2(c2, c3);
        }
        nbar_sync(barA, 128);   // psum ready within this half

        // ---- phase B (1 element/thread): reduce 4 kw, tanh, publish ----
        {
            const float* pb = psum + ((t & 1) * 2 + mw) * PS_HALF;
            float s0 = pre1;
            #pragma unroll
            for (int kk = 0; kk < 4; kk++)
                s0 += pb[kk * PS_KW + lb * PSROW + pbJ];
            float hv = tanhf(s0);
            size_t zidx = ((size_t)pbB * TT + t) * HH + jc * 8 + pbJ;
            z_out[zidx] = hv;
            __nv_bfloat16 zh = __float2bfloat16(hv);
            g_zhi[zidx] = zh;
            g_zlo[zidx] = __float2bfloat16(hv - __bfloat162float(zh));
        }

        // ---- z-done: kw=0 warp syncs + publishes; others arrive & fly ----
        if (kw == 0) {
            nbar_sync(barB, 128);
            if (lane == 0)
                flag_store(&g_flags[(blockIdx.x * 2 + mw) * 32], base + (unsigned)t + 1u);
        } else {
            nbar_arrive(barB, 128);
        }
    }
}

// ---------------- fp32 -> bf16 hi/lo split -----------------------------------
__global__ __launch_bounds__(256)
void split_bf16(const float* __restrict__ src,
                __nv_bfloat16* __restrict__ hi,
                __nv_bfloat16* __restrict__ lo, int n)
{
    int i = blockIdx.x * 256 + threadIdx.x;
    if (i < n) {
        float x = src[i];
        __nv_bfloat16 h = __float2bfloat16(x);
        hi[i] = h;
        lo[i] = __float2bfloat16(x - __bfloat162float(h));
    }
}

// ---------------- mma.sync bf16 3-split GEMM ---------------------------------
#define GT_BYTES  (128 * 80)
#define GBUF      (4 * GT_BYTES)
#define GSMEM     (2 * GBUF)

__global__ __launch_bounds__(256)
void bsgemm(int M, int N, int K,
            const __nv_bfloat16* __restrict__ Ahi, const __nv_bfloat16* __restrict__ Alo,
            const __nv_bfloat16* __restrict__ Bhi, const __nv_bfloat16* __restrict__ Blo,
            const float* __restrict__ bias1, const float* __restrict__ bias2,
            float* __restrict__ C)
{
    extern __shared__ __align__(16) char dsm[];
    const uint32_t sb = (uint32_t)__cvta_generic_to_shared(dsm);

    const int tid  = threadIdx.x;
    const int wid  = tid >> 5;
    const int lane = tid & 31;
    const int grp  = lane >> 2;
    const int tig  = lane & 3;
    const int wm   = wid & 1;
    const int wn   = wid >> 1;
    const int m0   = blockIdx.x * 128;
    const int n0   = blockIdx.y * 128;

    float acc[4][4][4];
    #pragma unroll
    for (int i = 0; i < 4; i++)
        #pragma unroll
        for (int j = 0; j < 4; j++)
            #pragma unroll
            for (int q = 0; q < 4; q++) acc[i][j][q] = 0.f;

    const int lrow = tid >> 2;
    const int lc16 = tid & 3;

    auto issue = [&](int kt, int buf) {
        #pragma unroll
        for (int r = 0; r < 2; r++) {
            int row = lrow + r * 64;
            uint32_t so = (uint32_t)buf * GBUF + row * 80 + lc16 * 16;
            size_t goA = (size_t)(m0 + row) * K + kt * 32 + lc16 * 8;
            size_t goB = (size_t)(n0 + row) * K + kt * 32 + lc16 * 8;
            cpa16(sb + so,                Ahi + goA);
            cpa16(sb + so + GT_BYTES,     Alo + goA);
            cpa16(sb + so + 2 * GT_BYTES, Bhi + goB);
            cpa16(sb + so + 3 * GT_BYTES, Blo + goB);
        }
        asm volatile("cp.async.commit_group;" ::: "memory");
    };

    const int KT = K >> 5;
    issue(0, 0);

    for (int kt = 0; kt < KT; kt++) {
        if (kt + 1 < KT) {
            issue(kt + 1, (kt + 1) & 1);
            asm volatile("cp.async.wait_group 1;" ::: "memory");
        } else {
            asm volatile("cp.async.wait_group 0;" ::: "memory");
        }
        __syncthreads();

        const uint32_t bufo = (uint32_t)(kt & 1) * GBUF;
        #pragma unroll
        for (int h16 = 0; h16 < 2; h16++) {
            uint32_t ah[4][4], al[4][4];
            #pragma unroll
            for (int mi = 0; mi < 4; mi++) {
                int row = wm * 64 + mi * 16 + grp;
                uint32_t base = sb + bufo + row * 80 + h16 * 32 + tig * 4;
                ah[mi][0] = lds32(base);
                ah[mi][1] = lds32(base + 8 * 80);
                ah[mi][2] = lds32(base + 16);
                ah[mi][3] = lds32(base + 8 * 80 + 16);
                al[mi][0] = lds32(base + GT_BYTES);
                al[mi][1] = lds32(base + GT_BYTES + 8 * 80);
                al[mi][2] = lds32(base + GT_BYTES + 16);
                al[mi][3] = lds32(base + GT_BYTES + 8 * 80 + 16);
            }
            uint32_t bh[4][2], bl[4][2];
            #pragma unroll
            for (int ni = 0; ni < 4; ni++) {
                int row = wn * 32 + ni * 8 + grp;
                uint32_t base = sb + bufo + 2 * GT_BYTES + row * 80 + h16 * 32 + tig * 4;
                bh[ni][0] = lds32(base);
                bh[ni][1] = lds32(base + 16);
                bl[ni][0] = lds32(base + GT_BYTES);
                bl[ni][1] = lds32(base + GT_BYTES + 16);
            }
            #pragma unroll
            for (int mi = 0; mi < 4; mi++)
                #pragma unroll
                for (int ni = 0; ni < 4; ni++) {
                    float* a = acc[mi][ni];
                    mma16816(a[0], a[1], a[2], a[3],
                             ah[mi][0], ah[mi][1], ah[mi][2], ah[mi][3],
                             bh[ni][0], bh[ni][1]);
                    mma16816(a[0], a[1], a[2], a[3],
                             ah[mi][0], ah[mi][1], ah[mi][2], ah[mi][3],
                             bl[ni][0], bl[ni][1]);
                    mma16816(a[0], a[1], a[2], a[3],
                             al[mi][0], al[mi][1], al[mi][2], al[mi][3],
                             bh[ni][0], bh[ni][1]);
                }
        }
        __syncthreads();
    }

    #pragma unroll
    for (int ni = 0; ni < 4; ni++) {
        int gc = n0 + wn * 32 + ni * 8 + tig * 2;
        float bs0 = 0.f, bs1 = 0.f;
        if (bias1) { bs0 += bias1[gc]; bs1 += bias1[gc + 1]; }
        if (bias2) { bs0 += bias2[gc]; bs1 += bias2[gc + 1]; }
        #pragma unroll
        for (int mi = 0; mi < 4; mi++) {
            int gr = m0 + wm * 64 + mi * 16 + grp;
            float* a = acc[mi][ni];
            *(float2*)&C[(size_t)gr * N + gc] = make_float2(a[0] + bs0, a[1] + bs1);
            *(float2*)&C[(size_t)(gr + 8) * N + gc] = make_float2(a[2] + bs0, a[3] + bs1);
        }
    }
}

// ---------------- row softmax over 512 cols ---------------------------------
__global__ __launch_bounds__(256)
void softmax512(const float* __restrict__ logits, float* __restrict__ out)
{
    const int row = blockIdx.x;
    const int tid = threadIdx.x;
    const float* in = logits + (size_t)row * OO;
    float a = in[tid], b = in[tid + 256];

    float m = fmaxf(a, b);
    #pragma unroll
    for (int o = 16; o > 0; o >>= 1)
        m = fmaxf(m, __shfl_xor_sync(0xffffffffu, m, o));
    __shared__ float redm[8];
    __shared__ float reds[8];
    if ((tid & 31) == 0) redm[tid >> 5] = m;
    __syncthreads();
    float mm = redm[0];
    #pragma unroll
    for (int i = 1; i < 8; i++) mm = fmaxf(mm, redm[i]);

    float e0 = expf(a - mm), e1 = expf(b - mm);
    float s = e0 + e1;
    #pragma unroll
    for (int o = 16; o > 0; o >>= 1)
        s += __shfl_xor_sync(0xffffffffu, s, o);
    if ((tid & 31) == 0) reds[tid >> 5] = s;
    __syncthreads();
    float ss = 0.f;
    #pragma unroll
    for (int i = 0; i < 8; i++) ss += reds[i];
    float inv = 1.0f / ss;

    float* op = out + (size_t)row * OO;
    op[tid]       = e0 * inv;
    op[tid + 256] = e1 * inv;
}

// ---------------- launch -----------------------------------------------------
extern "C" void kernel_launch(void* const* d_in, const int* in_sizes, int n_in,
                              void* d_out, int out_size)
{
    const float* x     = (const float*)d_in[0];
    const float* h0    = (const float*)d_in[1];
    const float* W_ih  = (const float*)d_in[2];
    const float* W_hh  = (const float*)d_in[3];
    const float* b_ih  = (const float*)d_in[4];
    const float* b_hh  = (const float*)d_in[5];
    const float* W_out = (const float*)d_in[6];
    const float* b_out = (const float*)d_in[7];
    float* out = (float*)d_out;

    float *pre, *logits, *zfb;
    cudaGetSymbolAddress((void**)&pre,    g_pre);
    cudaGetSymbolAddress((void**)&logits, g_logits);
    cudaGetSymbolAddress((void**)&zfb,    g_zfallback);
    __nv_bfloat16 *xhi, *xlo, *wih_hi, *wih_lo, *wout_hi, *wout_lo, *zhi, *zlo, *h0hi, *h0lo;
    cudaGetSymbolAddress((void**)&xhi, g_xhi);
    cudaGetSymbolAddress((void**)&xlo, g_xlo);
    cudaGetSymbolAddress((void**)&wih_hi, g_wih_hi);
    cudaGetSymbolAddress((void**)&wih_lo, g_wih_lo);
    cudaGetSymbolAddress((void**)&wout_hi, g_wout_hi);
    cudaGetSymbolAddress((void**)&wout_lo, g_wout_lo);
    cudaGetSymbolAddress((void**)&zhi, g_zhi);
    cudaGetSymbolAddress((void**)&zlo, g_zlo);
    cudaGetSymbolAddress((void**)&h0hi, g_h0hi);
    cudaGetSymbolAddress((void**)&h0lo, g_h0lo);

    cudaFuncSetAttribute(bsgemm, cudaFuncAttributeMaxDynamicSharedMemorySize, GSMEM);
    cudaFuncSetAttribute(rnn_persistent, cudaFuncAttributeMaxDynamicSharedMemorySize, RNN_SMEM);

    float* z = (out_size >= (int)((size_t)MM * (OO + HH)))
                 ? out + (size_t)MM * OO : zfb;

    // 0) bf16 hi/lo splits
    split_bf16<<<(MM * II + 255) / 256, 256>>>(x, xhi, xlo, MM * II);
    split_bf16<<<(HH * II + 255) / 256, 256>>>(W_ih, wih_hi, wih_lo, HH * II);
    split_bf16<<<(OO * HH + 255) / 256, 256>>>(W_out, wout_hi, wout_lo, OO * HH);
    split_bf16<<<(BB * HH + 255) / 256, 256>>>(h0, h0hi, h0lo, BB * HH);

    // 1) pre = x @ W_ih^T + b_ih + b_hh
    dim3 g1(MM / 128, HH / 128);
    bsgemm<<<g1, 256, GSMEM>>>(MM, HH, II, xhi, xlo, wih_hi, wih_lo, b_ih, b_hh, pre);

    // 2) recurrence (persistent, 128 blocks, dataflow half-flags)
    rnn_persistent<<<RNN_BLOCKS, 256, RNN_SMEM>>>(pre, W_hh, z);

    // 3) logits = z @ W_out^T + b_out
    dim3 g3(MM / 128, OO / 128);
    bsgemm<<<g3, 256, GSMEM>>>(MM, OO, HH, zhi, zlo, wout_hi, wout_lo, b_out, nullptr, logits);

    // 4) softmax rows -> out
    softmax512<<<MM, 256>>>(logits, out);
}

// round 11
// speedup vs baseline: 1.4470x; 1.4470x over previous
#include <cuda_runtime.h>
#include <cuda_bf16.h>
#include <cuda_fp16.h>
#include <cstdint>

// Problem dims
#define BB   32
#define TT   512
#define II   512
#define HH   1024
#define OO   512
#define MM   (BB*TT)

#define RNN_BLOCKS 64

// ---------------- scratch (static device globals) ---------------------------
__device__ float g_pre[MM * HH];
__device__ float g_logits[MM * OO];
__device__ float g_zfallback[MM * HH];

__device__ __nv_bfloat16 g_xhi[MM * II],    g_xlo[MM * II];
__device__ __nv_bfloat16 g_wih_hi[HH * II], g_wih_lo[HH * II];
__device__ __nv_bfloat16 g_wout_hi[OO * HH], g_wout_lo[OO * HH];
__device__ __nv_bfloat16 g_zhi[MM * HH],    g_zlo[MM * HH];

// fp16 recurrent state
__device__ __half g_zh16[MM * HH];
__device__ __half g_h0h16[BB * HH];

// per-(block, mw-half) spread flags (128B apart)
__device__ unsigned g_flags[RNN_BLOCKS * 2 * 32];

// ---------------- helpers ----------------------------------------------------
__device__ __forceinline__ void mma16816(float& d0, float& d1, float& d2, float& d3,
                                         uint32_t a0, uint32_t a1, uint32_t a2, uint32_t a3,
                                         uint32_t b0, uint32_t b1)
{
    asm volatile(
        "mma.sync.aligned.m16n8k16.row.col.f32.bf16.bf16.f32 "
        "{%0,%1,%2,%3},{%4,%5,%6,%7},{%8,%9},{%0,%1,%2,%3};"
        : "+f"(d0), "+f"(d1), "+f"(d2), "+f"(d3)
        : "r"(a0), "r"(a1), "r"(a2), "r"(a3), "r"(b0), "r"(b1));
}

__device__ __forceinline__ void mma16816h(float& d0, float& d1, float& d2, float& d3,
                                          uint32_t a0, uint32_t a1, uint32_t a2, uint32_t a3,
                                          uint32_t b0, uint32_t b1)
{
    asm volatile(
        "mma.sync.aligned.m16n8k16.row.col.f32.f16.f16.f32 "
        "{%0,%1,%2,%3},{%4,%5,%6,%7},{%8,%9},{%0,%1,%2,%3};"
        : "+f"(d0), "+f"(d1), "+f"(d2), "+f"(d3)
        : "r"(a0), "r"(a1), "r"(a2), "r"(a3), "r"(b0), "r"(b1));
}

__device__ __forceinline__ void ldsm4(uint32_t& r0, uint32_t& r1, uint32_t& r2, uint32_t& r3,
                                      uint32_t addr)
{
    asm volatile("ldmatrix.sync.aligned.m8n8.x4.shared.b16 {%0,%1,%2,%3}, [%4];"
                 : "=r"(r0), "=r"(r1), "=r"(r2), "=r"(r3) : "r"(addr));
}

__device__ __forceinline__ uint32_t lds32(uint32_t a) {
    uint32_t v;
    asm volatile("ld.shared.b32 %0, [%1];" : "=r"(v) : "r"(a));
    return v;
}

__device__ __forceinline__ void cpa16(uint32_t s, const void* g) {
    asm volatile("cp.async.cg.shared.global [%0], [%1], 16;" :: "r"(s), "l"(g));
}

__device__ __forceinline__ uint32_t pack_h2(float x, float y) {
    __half2 t = __floats2half2_rn(x, y);
    return *reinterpret_cast<uint32_t*>(&t);
}

__device__ __forceinline__ void flag_store(unsigned* p, unsigned v) {
    asm volatile("st.release.gpu.u32 [%0], %1;" :: "l"(p), "r"(v));
}
__device__ __forceinline__ void flag_wait(const unsigned* p, unsigned target) {
    unsigned v;
    do {
        asm volatile("ld.acquire.gpu.u32 %0, [%1];" : "=r"(v) : "l"(p));
    } while ((int)(v - target) < 0);
}

__device__ __forceinline__ void nbar_sync(int id, int cnt) {
    asm volatile("bar.sync %0, %1;" :: "r"(id), "r"(cnt) : "memory");
}
__device__ __forceinline__ void nbar_arrive(int id, int cnt) {
    asm volatile("bar.arrive %0, %1;" :: "r"(id), "r"(cnt) : "memory");
}

// ---------------- persistent Elman recurrence (fp16 state, dataflow) ---------
// 64 blocks x 256 threads, 1/SM. Block jc owns j in [jc*16, jc*16+16).
// 8 warps: kw=wid&3 (k chunk of 256), mw=wid>>2 (b half of 16).
// State h is SINGLE fp16 (eps 2^-11 -> final rel_err ~2e-4). W_hh lives in
// registers as fp16 fragments. Per step: poll 16 producer half-flags (1/lane),
// stage private 16x256 fp16 slice (8448B), 32 HMMA, half-scope psum reduce,
// phase B publishes z fp32 + packed fp16. kw=0 syncs+publishes; others fly.
#define WBUF   8448                    // per-warp fp16 slice
#define SM_PS  (8 * WBUF)              // 67584
#define PSROW  18
#define PS_KW  (16 * PSROW)
#define PS_HALF (4 * PS_KW)
#define RNN_SMEM (SM_PS + 2 * 2 * PS_HALF * 4)

__global__ __launch_bounds__(256, 1)
void rnn_persistent(const float* __restrict__ pre,
                    const float* __restrict__ W_hh,
                    float* __restrict__ z_out)
{
    extern __shared__ __align__(16) char dsm[];
    const uint32_t sb = (uint32_t)__cvta_generic_to_shared(dsm);

    const int tid  = threadIdx.x;
    const int wid  = tid >> 5;
    const int lane = tid & 31;
    const int grp  = lane >> 2;       // 0..7
    const int tig  = lane & 3;        // 0..3
    const int jc   = blockIdx.x;      // 0..63
    const int kw   = wid & 3;         // k chunk of 256
    const int mw   = wid >> 2;        // b half

    // replay-safe base (all flags equal at launch start)
    const unsigned base = g_flags[blockIdx.x * 64];

    // ---- preload W fragments (fp16) into registers, whole run ----
    uint32_t w0[2][16], w1[2][16];
    #pragma unroll
    for (int nt = 0; nt < 2; nt++) {
        const int jrow = jc * 16 + nt * 8 + grp;
        const float* Wr = W_hh + (size_t)jrow * HH + kw * 256;
        #pragma unroll
        for (int ki = 0; ki < 16; ki++) {
            int k0 = ki * 16 + tig * 2;
            w0[nt][ki] = pack_h2(Wr[k0],     Wr[k0 + 1]);
            w1[nt][ki] = pack_h2(Wr[k0 + 8], Wr[k0 + 9]);
        }
    }

    // warp-private staging buffer
    const uint32_t wb = sb + (uint32_t)wid * WBUF;
    const uint32_t lrow = (lane & 7) + ((lane >> 3) & 1) * 8;
    const uint32_t aoff = lrow * 528 + ((uint32_t)lane >> 4) * 16;

    // producer half-flag this lane polls: 16 producers cover k in [kw*256,+256)
    const int pflag = ((kw * 16 + (lane & 15)) * 2 + mw) * 32;

    // phase-B mapping within the 128-thread half
    const int ltid = tid & 127;
    const int lb   = ltid >> 3;               // local b 0..15
    const int pbB  = mw * 16 + lb;            // global b
    const int pbJ  = (ltid & 7) * 2;          // j pair within chunk

    float* const psum = (float*)(dsm + SM_PS);   // [parity][mw][kw][16][PSROW]

    const int barA = 1 + mw;   // psum-ready
    const int barB = 3 + mw;   // z-done

    for (int t = 0; t < TT; t++) {
        // prefetch pre (phase-B input, independent of h)
        float2 pre2 = *(const float2*)&pre[((size_t)pbB * TT + t) * HH + jc * 16 + pbJ];

        // ---- dataflow wait: this warp's 16 producer half-flags ----
        if (t > 0)
            flag_wait(&g_flags[pflag], base + (unsigned)t);
        __syncwarp();

        // ---- stage own 16-row x 256-k fp16 slice ----
        {
            const __half* sh;
            size_t rstride, off0;
            if (t == 0) {
                sh = g_h0h16;
                rstride = HH;
                off0 = (size_t)(mw * 16) * HH + kw * 256;
            } else {
                sh = g_zh16;
                rstride = (size_t)TT * HH;
                off0 = ((size_t)(mw * 16) * TT + (t - 1)) * HH + kw * 256;
            }
            #pragma unroll
            for (int i = 0; i < 16; i++) {
                int chunk = i * 32 + lane;
                int row   = chunk >> 5;
                int c     = chunk & 31;
                cpa16(wb + row * 528 + c * 16, sh + off0 + (size_t)row * rstride + c * 8);
            }
            asm volatile("cp.async.commit_group;" ::: "memory");
            asm volatile("cp.async.wait_group 0;" ::: "memory");
            __syncwarp();
        }

        // ---- mma over own k=256 (single fp16 term) ----
        float a1[2][4] = {{0,0,0,0},{0,0,0,0}};
        #pragma unroll
        for (int ki = 0; ki < 16; ki++) {
            uint32_t h0r, h1r, h2r, h3r;
            ldsm4(h0r, h1r, h2r, h3r, wb + aoff + ki * 32);
            #pragma unroll
            for (int nt = 0; nt < 2; nt++) {
                mma16816h(a1[nt][0], a1[nt][1], a1[nt][2], a1[nt][3],
                          h0r, h1r, h2r, h3r, w0[nt][ki], w1[nt][ki]);
            }
        }

        // ---- per-warp k-partials to SMEM (parity double-buffered) ----
        {
            float* pb = psum + ((t & 1) * 2 + mw) * PS_HALF + kw * PS_KW;
            #pragma unroll
            for (int nt = 0; nt < 2; nt++) {
                int jj = nt * 8 + tig * 2;
                float* p = pb + grp * PSROW + jj;
                *(float2*)p               = make_float2(a1[nt][0], a1[nt][1]);
                *(float2*)(p + 8 * PSROW) = make_float2(a1[nt][2], a1[nt][3]);
            }
        }
        nbar_sync(barA, 128);   // psum ready within this half

        // ---- phase B (2 elements/thread): reduce 4 kw, tanh, publish ----
        {
            const float* pb = psum + ((t & 1) * 2 + mw) * PS_HALF;
            float s0 = pre2.x, s1 = pre2.y;
            #pragma unroll
            for (int kk = 0; kk < 4; kk++) {
                float2 p = *(float2*)&pb[kk * PS_KW + lb * PSROW + pbJ];
                s0 += p.x; s1 += p.y;
            }
            float h0v = tanhf(s0);
            float h1v = tanhf(s1);
            size_t zidx = ((size_t)pbB * TT + t) * HH + jc * 16 + pbJ;
            *(uint32_t*)&g_zh16[zidx] = pack_h2(h0v, h1v);
            *(float2*)&z_out[zidx]    = make_float2(h0v, h1v);
        }

        // ---- z-done: kw=0 warp syncs + publishes; others arrive & fly ----
        if (kw == 0) {
            nbar_sync(barB, 128);
            if (lane == 0)
                flag_store(&g_flags[(blockIdx.x * 2 + mw) * 32], base + (unsigned)t + 1u);
        } else {
            nbar_arrive(barB, 128);
        }
    }
}

// ---------------- fp32 -> bf16 hi/lo split -----------------------------------
__global__ __launch_bounds__(256)
void split_bf16(const float* __restrict__ src,
                __nv_bfloat16* __restrict__ hi,
                __nv_bfloat16* __restrict__ lo, int n)
{
    int i = blockIdx.x * 256 + threadIdx.x;
    if (i < n) {
        float x = src[i];
        __nv_bfloat16 h = __float2bfloat16(x);
        hi[i] = h;
        lo[i] = __float2bfloat16(x - __bfloat162float(h));
    }
}

// ---------------- fp32 -> fp16 convert ----------------------------------------
__global__ __launch_bounds__(256)
void conv_f16(const float* __restrict__ src, __half* __restrict__ dst, int n)
{
    int i = blockIdx.x * 256 + threadIdx.x;
    if (i < n) dst[i] = __float2half_rn(src[i]);
}

// ---------------- mma.sync bf16 3-split GEMM ---------------------------------
#define GT_BYTES  (128 * 80)
#define GBUF      (4 * GT_BYTES)
#define GSMEM     (2 * GBUF)

__global__ __launch_bounds__(256)
void bsgemm(int M, int N, int K,
            const __nv_bfloat16* __restrict__ Ahi, const __nv_bfloat16* __restrict__ Alo,
            const __nv_bfloat16* __restrict__ Bhi, const __nv_bfloat16* __restrict__ Blo,
            const float* __restrict__ bias1, const float* __restrict__ bias2,
            float* __restrict__ C)
{
    extern __shared__ __align__(16) char dsm[];
    const uint32_t sb = (uint32_t)__cvta_generic_to_shared(dsm);

    const int tid  = threadIdx.x;
    const int wid  = tid >> 5;
    const int lane = tid & 31;
    const int grp  = lane >> 2;
    const int tig  = lane & 3;
    const int wm   = wid & 1;
    const int wn   = wid >> 1;
    const int m0   = blockIdx.x * 128;
    const int n0   = blockIdx.y * 128;

    float acc[4][4][4];
    #pragma unroll
    for (int i = 0; i < 4; i++)
        #pragma unroll
        for (int j = 0; j < 4; j++)
            #pragma unroll
            for (int q = 0; q < 4; q++) acc[i][j][q] = 0.f;

    const int lrow = tid >> 2;
    const int lc16 = tid & 3;

    auto issue = [&](int kt, int buf) {
        #pragma unroll
        for (int r = 0; r < 2; r++) {
            int row = lrow + r * 64;
            uint32_t so = (uint32_t)buf * GBUF + row * 80 + lc16 * 16;
            size_t goA = (size_t)(m0 + row) * K + kt * 32 + lc16 * 8;
            size_t goB = (size_t)(n0 + row) * K + kt * 32 + lc16 * 8;
            cpa16(sb + so,                Ahi + goA);
            cpa16(sb + so + GT_BYTES,     Alo + goA);
            cpa16(sb + so + 2 * GT_BYTES, Bhi + goB);
            cpa16(sb + so + 3 * GT_BYTES, Blo + goB);
        }
        asm volatile("cp.async.commit_group;" ::: "memory");
    };

    const int KT = K >> 5;
    issue(0, 0);

    for (int kt = 0; kt < KT; kt++) {
        if (kt + 1 < KT) {
            issue(kt + 1, (kt + 1) & 1);
            asm volatile("cp.async.wait_group 1;" ::: "memory");
        } else {
            asm volatile("cp.async.wait_group 0;" ::: "memory");
        }
        __syncthreads();

        const uint32_t bufo = (uint32_t)(kt & 1) * GBUF;
        #pragma unroll
        for (int h16 = 0; h16 < 2; h16++) {
            uint32_t ah[4][4], al[4][4];
            #pragma unroll
            for (int mi = 0; mi < 4; mi++) {
                int row = wm * 64 + mi * 16 + grp;
                uint32_t base = sb + bufo + row * 80 + h16 * 32 + tig * 4;
                ah[mi][0] = lds32(base);
                ah[mi][1] = lds32(base + 8 * 80);
                ah[mi][2] = lds32(base + 16);
                ah[mi][3] = lds32(base + 8 * 80 + 16);
                al[mi][0] = lds32(base + GT_BYTES);
                al[mi][1] = lds32(base + GT_BYTES + 8 * 80);
                al[mi][2] = lds32(base + GT_BYTES + 16);
                al[mi][3] = lds32(base + GT_BYTES + 8 * 80 + 16);
            }
            uint32_t bh[4][2], bl[4][2];
            #pragma unroll
            for (int ni = 0; ni < 4; ni++) {
                int row = wn * 32 + ni * 8 + grp;
                uint32_t base = sb + bufo + 2 * GT_BYTES + row * 80 + h16 * 32 + tig * 4;
                bh[ni][0] = lds32(base);
                bh[ni][1] = lds32(base + 16);
                bl[ni][0] = lds32(base + GT_BYTES);
                bl[ni][1] = lds32(base + GT_BYTES + 16);
            }
            #pragma unroll
            for (int mi = 0; mi < 4; mi++)
                #pragma unroll
                for (int ni = 0; ni < 4; ni++) {
                    float* a = acc[mi][ni];
                    mma16816(a[0], a[1], a[2], a[3],
                             ah[mi][0], ah[mi][1], ah[mi][2], ah[mi][3],
                             bh[ni][0], bh[ni][1]);
                    mma16816(a[0], a[1], a[2], a[3],
                             ah[mi][0], ah[mi][1], ah[mi][2], ah[mi][3],
                             bl[ni][0], bl[ni][1]);
                    mma16816(a[0], a[1], a[2], a[3],
                             al[mi][0], al[mi][1], al[mi][2], al[mi][3],
                             bh[ni][0], bh[ni][1]);
                }
        }
        __syncthreads();
    }

    #pragma unroll
    for (int ni = 0; ni < 4; ni++) {
        int gc = n0 + wn * 32 + ni * 8 + tig * 2;
        float bs0 = 0.f, bs1 = 0.f;
        if (bias1) { bs0 += bias1[gc]; bs1 += bias1[gc + 1]; }
        if (bias2) { bs0 += bias2[gc]; bs1 += bias2[gc + 1]; }
        #pragma unroll
        for (int mi = 0; mi < 4; mi++) {
            int gr = m0 + wm * 64 + mi * 16 + grp;
            float* a = acc[mi][ni];
            *(float2*)&C[(size_t)gr * N + gc] = make_float2(a[0] + bs0, a[1] + bs1);
            *(float2*)&C[(size_t)(gr + 8) * N + gc] = make_float2(a[2] + bs0, a[3] + bs1);
        }
    }
}

// ---------------- row softmax over 512 cols ---------------------------------
__global__ __launch_bounds__(256)
void softmax512(const float* __restrict__ logits, float* __restrict__ out)
{
    const int row = blockIdx.x;
    const int tid = threadIdx.x;
    const float* in = logits + (size_t)row * OO;
    float a = in[tid], b = in[tid + 256];

    float m = fmaxf(a, b);
    #pragma unroll
    for (int o = 16; o > 0; o >>= 1)
        m = fmaxf(m, __shfl_xor_sync(0xffffffffu, m, o));
    __shared__ float redm[8];
    __shared__ float reds[8];
    if ((tid & 31) == 0) redm[tid >> 5] = m;
    __syncthreads();
    float mm = redm[0];
    #pragma unroll
    for (int i = 1; i < 8; i++) mm = fmaxf(mm, redm[i]);

    float e0 = expf(a - mm), e1 = expf(b - mm);
    float s = e0 + e1;
    #pragma unroll
    for (int o = 16; o > 0; o >>= 1)
        s += __shfl_xor_sync(0xffffffffu, s, o);
    if ((tid & 31) == 0) reds[tid >> 5] = s;
    __syncthreads();
    float ss = 0.f;
    #pragma unroll
    for (int i = 0; i < 8; i++) ss += reds[i];
    float inv = 1.0f / ss;

    float* op = out + (size_t)row * OO;
    op[tid]       = e0 * inv;
    op[tid + 256] = e1 * inv;
}

// ---------------- launch -----------------------------------------------------
extern "C" void kernel_launch(void* const* d_in, const int* in_sizes, int n_in,
                              void* d_out, int out_size)
{
    const float* x     = (const float*)d_in[0];
    const float* h0    = (const float*)d_in[1];
    const float* W_ih  = (const float*)d_in[2];
    const float* W_hh  = (const float*)d_in[3];
    const float* b_ih  = (const float*)d_in[4];
    const float* b_hh  = (const float*)d_in[5];
    const float* W_out = (const float*)d_in[6];
    const float* b_out = (const float*)d_in[7];
    float* out = (float*)d_out;

    float *pre, *logits, *zfb;
    cudaGetSymbolAddress((void**)&pre,    g_pre);
    cudaGetSymbolAddress((void**)&logits, g_logits);
    cudaGetSymbolAddress((void**)&zfb,    g_zfallback);
    __nv_bfloat16 *xhi, *xlo, *wih_hi, *wih_lo, *wout_hi, *wout_lo, *zhi, *zlo;
    cudaGetSymbolAddress((void**)&xhi, g_xhi);
    cudaGetSymbolAddress((void**)&xlo, g_xlo);
    cudaGetSymbolAddress((void**)&wih_hi, g_wih_hi);
    cudaGetSymbolAddress((void**)&wih_lo, g_wih_lo);
    cudaGetSymbolAddress((void**)&wout_hi, g_wout_hi);
    cudaGetSymbolAddress((void**)&wout_lo, g_wout_lo);
    cudaGetSymbolAddress((void**)&zhi, g_zhi);
    cudaGetSymbolAddress((void**)&zlo, g_zlo);
    __half *zh16, *h0h16;
    cudaGetSymbolAddress((void**)&zh16, g_zh16);
    cudaGetSymbolAddress((void**)&h0h16, g_h0h16);

    cudaFuncSetAttribute(bsgemm, cudaFuncAttributeMaxDynamicSharedMemorySize, GSMEM);
    cudaFuncSetAttribute(rnn_persistent, cudaFuncAttributeMaxDynamicSharedMemorySize, RNN_SMEM);

    float* z = (out_size >= (int)((size_t)MM * (OO + HH)))
                 ? out + (size_t)MM * OO : zfb;

    // 0) input splits / converts
    split_bf16<<<(MM * II + 255) / 256, 256>>>(x, xhi, xlo, MM * II);
    split_bf16<<<(HH * II + 255) / 256, 256>>>(W_ih, wih_hi, wih_lo, HH * II);
    split_bf16<<<(OO * HH + 255) / 256, 256>>>(W_out, wout_hi, wout_lo, OO * HH);
    conv_f16<<<(BB * HH + 255) / 256, 256>>>(h0, h0h16, BB * HH);

    // 1) pre = x @ W_ih^T + b_ih + b_hh
    dim3 g1(MM / 128, HH / 128);
    bsgemm<<<g1, 256, GSMEM>>>(MM, HH, II, xhi, xlo, wih_hi, wih_lo, b_ih, b_hh, pre);

    // 2) recurrence (persistent, fp16 state, dataflow half-flags)
    rnn_persistent<<<RNN_BLOCKS, 256, RNN_SMEM>>>(pre, W_hh, z);

    // 3) z -> bf16 hi/lo for the out-GEMM (off the critical chain)
    split_bf16<<<(MM * HH + 255) / 256, 256>>>(z, zhi, zlo, MM * HH);

    // 4) logits = z @ W_out^T + b_out
    dim3 g3(MM / 128, OO / 128);
    bsgemm<<<g3, 256, GSMEM>>>(MM, OO, HH, zhi, zlo, wout_hi, wout_lo, b_out, nullptr, logits);

    // 5) softmax rows -> out
    softmax512<<<MM, 256>>>(logits, out);
}